// round 1
// baseline (speedup 1.0000x reference)
#include <cuda_runtime.h>
#include <cstdint>

typedef unsigned long long ull;

#define N_ROWS 32768
#define K_CODES 4096
#define D_DIM   256

#define BM 128
#define BN 128
#define BK 16
#define SROW (BM + 4)   // padded smem row stride (132) to reduce bank conflicts

// Scratch (no allocations allowed in kernel_launch)
__device__ float g_cc[K_CODES];
__device__ float g_xx[N_ROWS];
__device__ int   g_best[N_ROWS];

// ---------------------------------------------------------------------------
// packed f32x2 helpers (FFMA2 path — ptxas never emits this from C++)
// ---------------------------------------------------------------------------
__device__ __forceinline__ ull pack2(float lo, float hi) {
    ull r;
    asm("mov.b64 %0, {%1, %2};" : "=l"(r) : "f"(lo), "f"(hi));
    return r;
}
__device__ __forceinline__ void unpack2(ull v, float& lo, float& hi) {
    asm("mov.b64 {%0, %1}, %2;" : "=f"(lo), "=f"(hi) : "l"(v));
}
__device__ __forceinline__ void fma2(ull& d, ull a, ull b) {
    asm("fma.rn.f32x2 %0, %1, %2, %0;" : "+l"(d) : "l"(a), "l"(b));
}

// ---------------------------------------------------------------------------
// Kernel 1: row norms. Replicates jnp.sum(v*v, axis=1): elementwise multiply
// (rounded) then sequential adds — NO fma contraction.
// ---------------------------------------------------------------------------
__global__ void norms_kernel(const float* __restrict__ x,
                             const float* __restrict__ cb) {
    int i = blockIdx.x * blockDim.x + threadIdx.x;
    if (i < K_CODES) {
        const float* r = cb + (size_t)i * D_DIM;
        float s = 0.0f;
#pragma unroll 8
        for (int d = 0; d < D_DIM; ++d) s = __fadd_rn(s, __fmul_rn(r[d], r[d]));
        g_cc[i] = s;
    }
    if (i < N_ROWS) {
        const float* r = x + (size_t)i * D_DIM;
        float s = 0.0f;
#pragma unroll 8
        for (int d = 0; d < D_DIM; ++d) s = __fadd_rn(s, __fmul_rn(r[d], r[d]));
        g_xx[i] = s;
    }
}

// ---------------------------------------------------------------------------
// Kernel 2: fused GEMM (X @ C^T) + argmin.
// Block: 128 rows x all 4096 codes (processed in 32 chunks of 128).
// Per-thread 8x8 micro-tile held as 32 packed f32x2 accumulators.
// Accumulation over d is strictly sequential (chunk order * in-chunk order),
// single accumulator per output -> deterministic fp32 FMA chain d=0..255.
// dist replicates reference rounding: fl(fl(xx + cc) + (-2*s)).
// Tie-break: strictly lower index wins (per-thread candidate order ascending;
// cross-thread reduce compares (dist, idx)).
// ---------------------------------------------------------------------------
union SmemU {
    struct {
        float Xs[2][BK][SROW];
        float Cs[2][BK][SROW];
    } t;
    struct {
        float rd[BM][16];
        int   ri[BM][16];
    } r;
};

__global__ __launch_bounds__(256, 2)
void vq_argmin_kernel(const float* __restrict__ x,
                      const float* __restrict__ cb) {
    __shared__ SmemU sm;
    __shared__ float sxx[BM];

    const int tid = threadIdx.x;
    const int tx  = tid & 15;   // code group (8 codes)
    const int ty  = tid >> 4;   // row  group (8 rows)
    const int rowBase = blockIdx.x * BM;

    if (tid < BM) sxx[tid] = g_xx[rowBase + tid];

    float best[8];
    int   bidx[8];
#pragma unroll
    for (int i = 0; i < 8; ++i) { best[i] = 3.4028235e38f; bidx[i] = 0; }

    const float4* x4  = reinterpret_cast<const float4*>(x);
    const float4* cb4 = reinterpret_cast<const float4*>(cb);

    // tile loader: 2048 floats = 512 float4, 2 per thread, stored transposed
    const int f0row = tid >> 2, f0seg = tid & 3;
    const int f1row = (tid + 256) >> 2, f1seg = tid & 3;  // (tid+256)&3 == tid&3

    for (int kt = 0; kt < K_CODES / BN; ++kt) {
        const int codeBase = kt * BN;

        ull acc[8][4];
#pragma unroll
        for (int i = 0; i < 8; ++i)
#pragma unroll
            for (int j = 0; j < 4; ++j) acc[i][j] = 0ULL;

        // prologue load of d-chunk 0
        {
            float4 vx0 = x4[(size_t)(rowBase + f0row) * (D_DIM / 4) + f0seg];
            float4 vx1 = x4[(size_t)(rowBase + f1row) * (D_DIM / 4) + f1seg];
            float4 vc0 = cb4[(size_t)(codeBase + f0row) * (D_DIM / 4) + f0seg];
            float4 vc1 = cb4[(size_t)(codeBase + f1row) * (D_DIM / 4) + f1seg];
            sm.t.Xs[0][f0seg * 4 + 0][f0row] = vx0.x;
            sm.t.Xs[0][f0seg * 4 + 1][f0row] = vx0.y;
            sm.t.Xs[0][f0seg * 4 + 2][f0row] = vx0.z;
            sm.t.Xs[0][f0seg * 4 + 3][f0row] = vx0.w;
            sm.t.Xs[0][f1seg * 4 + 0][f1row] = vx1.x;
            sm.t.Xs[0][f1seg * 4 + 1][f1row] = vx1.y;
            sm.t.Xs[0][f1seg * 4 + 2][f1row] = vx1.z;
            sm.t.Xs[0][f1seg * 4 + 3][f1row] = vx1.w;
            sm.t.Cs[0][f0seg * 4 + 0][f0row] = vc0.x;
            sm.t.Cs[0][f0seg * 4 + 1][f0row] = vc0.y;
            sm.t.Cs[0][f0seg * 4 + 2][f0row] = vc0.z;
            sm.t.Cs[0][f0seg * 4 + 3][f0row] = vc0.w;
            sm.t.Cs[0][f1seg * 4 + 0][f1row] = vc1.x;
            sm.t.Cs[0][f1seg * 4 + 1][f1row] = vc1.y;
            sm.t.Cs[0][f1seg * 4 + 2][f1row] = vc1.z;
            sm.t.Cs[0][f1seg * 4 + 3][f1row] = vc1.w;
        }
        __syncthreads();

        for (int dc = 0; dc < D_DIM / BK; ++dc) {
            const int cur = dc & 1;
            // prefetch next d-chunk into the other buffer
            if (dc + 1 < D_DIM / BK) {
                const int nb = cur ^ 1;
                const int dnext = dc + 1;
                float4 vx0 = x4[(size_t)(rowBase + f0row) * (D_DIM / 4) + dnext * 4 + f0seg];
                float4 vx1 = x4[(size_t)(rowBase + f1row) * (D_DIM / 4) + dnext * 4 + f1seg];
                float4 vc0 = cb4[(size_t)(codeBase + f0row) * (D_DIM / 4) + dnext * 4 + f0seg];
                float4 vc1 = cb4[(size_t)(codeBase + f1row) * (D_DIM / 4) + dnext * 4 + f1seg];
                sm.t.Xs[nb][f0seg * 4 + 0][f0row] = vx0.x;
                sm.t.Xs[nb][f0seg * 4 + 1][f0row] = vx0.y;
                sm.t.Xs[nb][f0seg * 4 + 2][f0row] = vx0.z;
                sm.t.Xs[nb][f0seg * 4 + 3][f0row] = vx0.w;
                sm.t.Xs[nb][f1seg * 4 + 0][f1row] = vx1.x;
                sm.t.Xs[nb][f1seg * 4 + 1][f1row] = vx1.y;
                sm.t.Xs[nb][f1seg * 4 + 2][f1row] = vx1.z;
                sm.t.Xs[nb][f1seg * 4 + 3][f1row] = vx1.w;
                sm.t.Cs[nb][f0seg * 4 + 0][f0row] = vc0.x;
                sm.t.Cs[nb][f0seg * 4 + 1][f0row] = vc0.y;
                sm.t.Cs[nb][f0seg * 4 + 2][f0row] = vc0.z;
                sm.t.Cs[nb][f0seg * 4 + 3][f0row] = vc0.w;
                sm.t.Cs[nb][f1seg * 4 + 0][f1row] = vc1.x;
                sm.t.Cs[nb][f1seg * 4 + 1][f1row] = vc1.y;
                sm.t.Cs[nb][f1seg * 4 + 2][f1row] = vc1.z;
                sm.t.Cs[nb][f1seg * 4 + 3][f1row] = vc1.w;
            }

#pragma unroll
            for (int kk = 0; kk < BK; ++kk) {
                float4 a0 = *reinterpret_cast<const float4*>(&sm.t.Xs[cur][kk][ty * 8]);
                float4 a1 = *reinterpret_cast<const float4*>(&sm.t.Xs[cur][kk][ty * 8 + 4]);
                float4 b0 = *reinterpret_cast<const float4*>(&sm.t.Cs[cur][kk][tx * 8]);
                float4 b1 = *reinterpret_cast<const float4*>(&sm.t.Cs[cur][kk][tx * 8 + 4]);
                ull aa[8];
                aa[0] = pack2(a0.x, a0.x); aa[1] = pack2(a0.y, a0.y);
                aa[2] = pack2(a0.z, a0.z); aa[3] = pack2(a0.w, a0.w);
                aa[4] = pack2(a1.x, a1.x); aa[5] = pack2(a1.y, a1.y);
                aa[6] = pack2(a1.z, a1.z); aa[7] = pack2(a1.w, a1.w);
                ull bb[4];
                bb[0] = pack2(b0.x, b0.y); bb[1] = pack2(b0.z, b0.w);
                bb[2] = pack2(b1.x, b1.y); bb[3] = pack2(b1.z, b1.w);
#pragma unroll
                for (int i = 0; i < 8; ++i)
#pragma unroll
                    for (int j = 0; j < 4; ++j)
                        fma2(acc[i][j], aa[i], bb[j]);
            }
            __syncthreads();
        }

        // epilogue: distances + running argmin (ascending code order per thread)
#pragma unroll
        for (int j = 0; j < 4; ++j) {
            const int c0 = codeBase + tx * 8 + j * 2;
            const float cc0 = g_cc[c0];
            const float cc1 = g_cc[c0 + 1];
#pragma unroll
            for (int i = 0; i < 8; ++i) {
                float s0, s1;
                unpack2(acc[i][j], s0, s1);
                const float xxv = sxx[ty * 8 + i];
                // replicate reference rounding: fl(fl(xx+cc) - fl(2*s))
                const float d0 = __fadd_rn(__fadd_rn(xxv, cc0), __fmul_rn(-2.0f, s0));
                const float d1 = __fadd_rn(__fadd_rn(xxv, cc1), __fmul_rn(-2.0f, s1));
                if (d0 < best[i]) { best[i] = d0; bidx[i] = c0; }
                if (d1 < best[i]) { best[i] = d1; bidx[i] = c0 + 1; }
            }
        }
    }

    // cross-thread reduction per row: min by (dist, then index)
    __syncthreads();
#pragma unroll
    for (int i = 0; i < 8; ++i) {
        sm.r.rd[ty * 8 + i][tx] = best[i];
        sm.r.ri[ty * 8 + i][tx] = bidx[i];
    }
    __syncthreads();
    if (tid < BM) {
        float b  = sm.r.rd[tid][0];
        int   bi = sm.r.ri[tid][0];
#pragma unroll
        for (int t = 1; t < 16; ++t) {
            const float d  = sm.r.rd[tid][t];
            const int   di = sm.r.ri[tid][t];
            if (d < b || (d == b && di < bi)) { b = d; bi = di; }
        }
        g_best[rowBase + tid] = bi;
    }
}

// ---------------------------------------------------------------------------
// Kernel 3: gather out[n] = codebook[best[n]]  (forward value of STE output)
// ---------------------------------------------------------------------------
__global__ void gather_kernel(const float* __restrict__ cb,
                              float* __restrict__ out) {
    const int idx = blockIdx.x * blockDim.x + threadIdx.x;  // over N*64 float4
    const int row = idx >> 6;
    const int seg = idx & 63;
    const int code = g_best[row];
    reinterpret_cast<float4*>(out)[idx] =
        reinterpret_cast<const float4*>(cb)[(size_t)code * 64 + seg];
}

// ---------------------------------------------------------------------------
extern "C" void kernel_launch(void* const* d_in, const int* in_sizes, int n_in,
                              void* d_out, int out_size) {
    const float* x  = (const float*)d_in[0];
    const float* cb = (const float*)d_in[1];
    // defensive: metadata order should be (x, codebook); swap if sizes say otherwise
    if (n_in >= 2 && in_sizes[0] == K_CODES * D_DIM && in_sizes[1] == N_ROWS * D_DIM) {
        const float* t = x; x = cb; cb = t;
    }
    float* out = (float*)d_out;

    norms_kernel<<<(N_ROWS + 255) / 256, 256>>>(x, cb);
    vq_argmin_kernel<<<N_ROWS / BM, 256>>>(x, cb);
    gather_kernel<<<(N_ROWS * 64) / 256, 256>>>(cb, out);
}